// round 1
// baseline (speedup 1.0000x reference)
#include <cuda_runtime.h>
#include <math.h>

// Problem constants
#define S_LEN 2048
#define HID   1024
#define NHEAD 16
#define HDIM  64
#define SH    (S_LEN * HID)
#define ATT_SCALE 0.125f   // 1/sqrt(64)

// ---------------------------------------------------------------------------
// Scratch (device globals; no allocation allowed in kernel_launch)
// ---------------------------------------------------------------------------
__device__ float g_q[SH];
__device__ float g_k[SH];
__device__ float g_v[SH];
__device__ float g_ctx[SH];
__device__ float g_out[SH];
__device__ float g_rq[SH];
__device__ float g_rk[2 * SH];
__device__ float g_rv[2 * SH];
__device__ float g_rctx[2 * SH];
__device__ float g_rec[SH];
__device__ float g_gpre[SH];

// ---------------------------------------------------------------------------
// GEMM: C[M,N] = A[M,K] @ B[K,N] (+ bias) (+ C if accumulate)
// 128x128 tile, BK=8, 256 threads, 8x8 register tile per thread.
// ---------------------------------------------------------------------------
#define GBM 128
#define GBN 128
#define GBK 8

__global__ void __launch_bounds__(256) gemm_kernel(
    const float* __restrict__ A, const float* __restrict__ B,
    const float* __restrict__ bias, float* __restrict__ C,
    int M, int N, int K, int accumulate)
{
    __shared__ float As[GBK][GBM];
    __shared__ float Bs[GBK][GBN];

    const int tid = threadIdx.x;
    const int ty = tid >> 4;        // 0..15
    const int tx = tid & 15;        // 0..15
    const int m0 = blockIdx.y * GBM;
    const int n0 = blockIdx.x * GBN;

    // Loader mapping
    const int arow = tid >> 1;             // 0..127
    const int akq  = (tid & 1) << 2;       // 0 or 4
    const int brow = tid >> 5;             // 0..7
    const int bcol = (tid & 31) << 2;      // 0..124

    const float* Aptr = A + (size_t)(m0 + arow) * K + akq;
    const float* Bptr = B + (size_t)brow * N + n0 + bcol;

    float acc[8][8];
    #pragma unroll
    for (int i = 0; i < 8; i++)
        #pragma unroll
        for (int j = 0; j < 8; j++) acc[i][j] = 0.0f;

    for (int kt = 0; kt < K; kt += GBK) {
        float4 av = *(const float4*)(Aptr + kt);
        As[akq + 0][arow] = av.x;
        As[akq + 1][arow] = av.y;
        As[akq + 2][arow] = av.z;
        As[akq + 3][arow] = av.w;
        *(float4*)&Bs[brow][bcol] = *(const float4*)(Bptr + (size_t)kt * N);
        __syncthreads();

        #pragma unroll
        for (int k = 0; k < GBK; k++) {
            float a[8], b[8];
            *(float4*)(a)     = *(const float4*)&As[k][ty * 8];
            *(float4*)(a + 4) = *(const float4*)&As[k][ty * 8 + 4];
            *(float4*)(b)     = *(const float4*)&Bs[k][tx * 8];
            *(float4*)(b + 4) = *(const float4*)&Bs[k][tx * 8 + 4];
            #pragma unroll
            for (int i = 0; i < 8; i++)
                #pragma unroll
                for (int j = 0; j < 8; j++)
                    acc[i][j] += a[i] * b[j];
        }
        __syncthreads();
    }

    // Epilogue
    #pragma unroll
    for (int i = 0; i < 8; i++) {
        size_t row = (size_t)(m0 + ty * 8 + i) * N + n0 + tx * 8;
        #pragma unroll
        for (int j = 0; j < 8; j++) {
            float v = acc[i][j];
            if (bias) v += bias[n0 + tx * 8 + j];
            if (accumulate) v += C[row + j];
            C[row + j] = v;
        }
    }
}

// ---------------------------------------------------------------------------
// Flash attention (full, no mask): per (query-tile of 64, head).
// Q,K,V,O all in [S, H] layout; head h occupies columns [h*64, h*64+64).
// 256 threads as 16x16, 4x4 register tiles, online softmax.
// ---------------------------------------------------------------------------
#define AM 64
#define AN 64
#define APITCH 68
#define ATTN_SMEM (4 * AM * APITCH * 4)   // Qs, Ks, Vs, Ps

__global__ void __launch_bounds__(256) attn_kernel(
    const float* __restrict__ Q, const float* __restrict__ K,
    const float* __restrict__ V, float* __restrict__ O)
{
    extern __shared__ float sm[];
    float* Qs = sm;                       // [AM][APITCH]
    float* Ks = Qs + AM * APITCH;         // [AN][APITCH]
    float* Vs = Ks + AN * APITCH;         // [AN][APITCH]
    float* Ps = Vs + AN * APITCH;         // [AM][APITCH]

    const int tid = threadIdx.x;
    const int ty = tid >> 4;              // 0..15
    const int tx = tid & 15;              // 0..15
    const int hoff = blockIdx.y * HDIM;
    const int q0 = blockIdx.x * AM;

    // Load Q tile (64 rows x 64 cols) with float4
    {
        const int r  = tid >> 4;
        const int d4 = (tid & 15) << 2;
        #pragma unroll
        for (int rr = r; rr < AM; rr += 16) {
            *(float4*)&Qs[rr * APITCH + d4] =
                *(const float4*)(Q + (size_t)(q0 + rr) * HID + hoff + d4);
        }
    }

    float o[4][4];
    float m[4], l[4];
    #pragma unroll
    for (int i = 0; i < 4; i++) {
        m[i] = -1e30f; l[i] = 0.0f;
        #pragma unroll
        for (int j = 0; j < 4; j++) o[i][j] = 0.0f;
    }
    __syncthreads();

    for (int kt = 0; kt < S_LEN; kt += AN) {
        // Load K, V tiles
        {
            const int r  = tid >> 4;
            const int d4 = (tid & 15) << 2;
            #pragma unroll
            for (int rr = r; rr < AN; rr += 16) {
                *(float4*)&Ks[rr * APITCH + d4] =
                    *(const float4*)(K + (size_t)(kt + rr) * HID + hoff + d4);
                *(float4*)&Vs[rr * APITCH + d4] =
                    *(const float4*)(V + (size_t)(kt + rr) * HID + hoff + d4);
            }
        }
        __syncthreads();

        // S = Q K^T  (4x4 per thread)
        float s[4][4];
        #pragma unroll
        for (int i = 0; i < 4; i++)
            #pragma unroll
            for (int j = 0; j < 4; j++) s[i][j] = 0.0f;

        #pragma unroll
        for (int d = 0; d < HDIM; d += 4) {
            float4 qv[4], kv[4];
            #pragma unroll
            for (int i = 0; i < 4; i++)
                qv[i] = *(const float4*)&Qs[(ty * 4 + i) * APITCH + d];
            #pragma unroll
            for (int j = 0; j < 4; j++)
                kv[j] = *(const float4*)&Ks[(tx * 4 + j) * APITCH + d];
            #pragma unroll
            for (int i = 0; i < 4; i++)
                #pragma unroll
                for (int j = 0; j < 4; j++) {
                    s[i][j] += qv[i].x * kv[j].x;
                    s[i][j] += qv[i].y * kv[j].y;
                    s[i][j] += qv[i].z * kv[j].z;
                    s[i][j] += qv[i].w * kv[j].w;
                }
        }

        // Online softmax (per row, reduce across the 16 tx lanes)
        #pragma unroll
        for (int i = 0; i < 4; i++) {
            float mx = -1e30f;
            #pragma unroll
            for (int j = 0; j < 4; j++) {
                s[i][j] *= ATT_SCALE;
                mx = fmaxf(mx, s[i][j]);
            }
            #pragma unroll
            for (int off = 8; off > 0; off >>= 1)
                mx = fmaxf(mx, __shfl_xor_sync(0xffffffffu, mx, off));

            float mnew  = fmaxf(m[i], mx);
            float alpha = __expf(m[i] - mnew);
            float rs = 0.0f;
            #pragma unroll
            for (int j = 0; j < 4; j++) {
                float p = __expf(s[i][j] - mnew);
                Ps[(ty * 4 + i) * APITCH + tx * 4 + j] = p;
                rs += p;
            }
            #pragma unroll
            for (int off = 8; off > 0; off >>= 1)
                rs += __shfl_xor_sync(0xffffffffu, rs, off);

            l[i] = l[i] * alpha + rs;
            m[i] = mnew;
            #pragma unroll
            for (int j = 0; j < 4; j++) o[i][j] *= alpha;
        }
        __syncthreads();

        // O += P @ V
        #pragma unroll 8
        for (int c = 0; c < AN; c++) {
            float4 vv = *(const float4*)&Vs[c * APITCH + tx * 4];
            #pragma unroll
            for (int i = 0; i < 4; i++) {
                float p = Ps[(ty * 4 + i) * APITCH + c];
                o[i][0] += p * vv.x;
                o[i][1] += p * vv.y;
                o[i][2] += p * vv.z;
                o[i][3] += p * vv.w;
            }
        }
        __syncthreads();
    }

    // Write out O / l
    #pragma unroll
    for (int i = 0; i < 4; i++) {
        float inv = 1.0f / l[i];
        float4 r;
        r.x = o[i][0] * inv; r.y = o[i][1] * inv;
        r.z = o[i][2] * inv; r.w = o[i][3] * inv;
        *(float4*)(O + (size_t)(q0 + ty * 4 + i) * HID + hoff + tx * 4) = r;
    }
}

// ---------------------------------------------------------------------------
// Elementwise kernels
// ---------------------------------------------------------------------------
__global__ void combine_kernel(const float4* __restrict__ a,
                               const float4* __restrict__ b,
                               float4* __restrict__ o, int n4)
{
    int i = blockIdx.x * blockDim.x + threadIdx.x;
    if (i < n4) {
        float4 x = a[i], y = b[i], r;
        r.x = 0.5f * (x.x + y.x); r.y = 0.5f * (x.y + y.y);
        r.z = 0.5f * (x.z + y.z); r.w = 0.5f * (x.w + y.w);
        o[i] = r;
    }
}

__device__ __forceinline__ float sigmoidf_(float x) {
    return 1.0f / (1.0f + __expf(-x));
}

__global__ void gate_kernel(const float4* __restrict__ o,
                            const float4* __restrict__ rec,
                            const float4* __restrict__ gp,
                            float4* __restrict__ out, int n4)
{
    int i = blockIdx.x * blockDim.x + threadIdx.x;
    if (i < n4) {
        float4 ov = o[i], rv = rec[i], gv = gp[i], r;
        r.x = ov.x + sigmoidf_(gv.x) * (rv.x - ov.x);
        r.y = ov.y + sigmoidf_(gv.y) * (rv.y - ov.y);
        r.z = ov.z + sigmoidf_(gv.z) * (rv.z - ov.z);
        r.w = ov.w + sigmoidf_(gv.w) * (rv.w - ov.w);
        out[i] = r;
    }
}

// ---------------------------------------------------------------------------
// Launch
// ---------------------------------------------------------------------------
extern "C" void kernel_launch(void* const* d_in, const int* in_sizes, int n_in,
                              void* d_out, int out_size)
{
    (void)in_sizes; (void)n_in; (void)out_size;

    const float* hs   = (const float*)d_in[0];
    const float* past = (const float*)d_in[1];
    const float* Wq = (const float*)d_in[2];  const float* bq = (const float*)d_in[3];
    const float* Wk = (const float*)d_in[4];  const float* bk = (const float*)d_in[5];
    const float* Wv = (const float*)d_in[6];  const float* bv = (const float*)d_in[7];
    const float* Wo = (const float*)d_in[8];  const float* bo = (const float*)d_in[9];
    const float* Wrq = (const float*)d_in[10]; const float* brq = (const float*)d_in[11];
    const float* Wrk = (const float*)d_in[12]; const float* brk = (const float*)d_in[13];
    const float* Wrv = (const float*)d_in[14]; const float* brv = (const float*)d_in[15];
    const float* Wg = (const float*)d_in[16];  const float* bg = (const float*)d_in[17];

    float *q, *k, *v, *ctx, *out, *rq, *rk, *rv, *rctx, *rec, *gpre;
    cudaGetSymbolAddress((void**)&q,    g_q);
    cudaGetSymbolAddress((void**)&k,    g_k);
    cudaGetSymbolAddress((void**)&v,    g_v);
    cudaGetSymbolAddress((void**)&ctx,  g_ctx);
    cudaGetSymbolAddress((void**)&out,  g_out);
    cudaGetSymbolAddress((void**)&rq,   g_rq);
    cudaGetSymbolAddress((void**)&rk,   g_rk);
    cudaGetSymbolAddress((void**)&rv,   g_rv);
    cudaGetSymbolAddress((void**)&rctx, g_rctx);
    cudaGetSymbolAddress((void**)&rec,  g_rec);
    cudaGetSymbolAddress((void**)&gpre, g_gpre);

    cudaFuncSetAttribute(attn_kernel,
                         cudaFuncAttributeMaxDynamicSharedMemorySize, ATTN_SMEM);

    dim3 ggrid(HID / GBN, S_LEN / GBM);       // (8, 16)
    dim3 ggrid2(HID / GBN, 2 * S_LEN / GBM);  // (8, 32)
    dim3 agrid(S_LEN / AM, NHEAD);            // (32, 16)
    const int n4 = SH / 4;
    const int eblk = 256;
    const int egrd = (n4 + eblk - 1) / eblk;

    // --- self attention ---
    gemm_kernel<<<ggrid, 256>>>(hs, Wq, bq, q, S_LEN, HID, HID, 0);
    gemm_kernel<<<ggrid, 256>>>(hs, Wk, bk, k, S_LEN, HID, HID, 0);
    gemm_kernel<<<ggrid, 256>>>(hs, Wv, bv, v, S_LEN, HID, HID, 0);
    attn_kernel<<<agrid, 256, ATTN_SMEM>>>(q, k, v, ctx);
    gemm_kernel<<<ggrid, 256>>>(ctx, Wo, bo, out, S_LEN, HID, HID, 0);

    // --- recursive attention ---
    gemm_kernel<<<ggrid, 256>>>(out, Wrq, brq, rq, S_LEN, HID, HID, 0);
    gemm_kernel<<<ggrid2, 256>>>(past, Wrk, brk, rk, 2 * S_LEN, HID, HID, 0);
    gemm_kernel<<<ggrid2, 256>>>(past, Wrv, brv, rv, 2 * S_LEN, HID, HID, 0);
    attn_kernel<<<agrid, 256, ATTN_SMEM>>>(rq, rk,      rv,      rctx);
    attn_kernel<<<agrid, 256, ATTN_SMEM>>>(rq, rk + SH, rv + SH, rctx + SH);
    combine_kernel<<<egrd, eblk>>>((const float4*)rctx, (const float4*)(rctx + SH),
                                   (float4*)rec, n4);

    // --- gate: gpre = [out, rec] @ Wg + bg  (split Wg) ---
    gemm_kernel<<<ggrid, 256>>>(out, Wg, bg, gpre, S_LEN, HID, HID, 0);
    gemm_kernel<<<ggrid, 256>>>(rec, Wg + (size_t)HID * HID, nullptr, gpre,
                                S_LEN, HID, HID, 1);

    // --- final blend ---
    gate_kernel<<<egrd, eblk>>>((const float4*)out, (const float4*)rec,
                                (const float4*)gpre, (float4*)d_out, n4);
}

// round 3
// speedup vs baseline: 2.5592x; 2.5592x over previous
#include <cuda_runtime.h>
#include <math.h>
#include <stdint.h>

// Problem constants
#define S_LEN 2048
#define HID   1024
#define NHEAD 16
#define HDIM  64
#define SH    (S_LEN * HID)
#define ATT_SCALE 0.125f   // 1/sqrt(64)

// ---------------------------------------------------------------------------
// Scratch (device globals; no allocation allowed in kernel_launch)
// ---------------------------------------------------------------------------
__device__ float g_q[SH];
__device__ float g_k[SH];
__device__ float g_v[SH];
__device__ float g_ctx[SH];
__device__ float g_out[SH];
__device__ float g_rq[SH];
__device__ float g_rk[2 * SH];
__device__ float g_rv[2 * SH];
__device__ float g_rctx[2 * SH];
__device__ float g_rec[SH];
__device__ float g_gpre[SH];

// ---------------------------------------------------------------------------
// tf32 helpers
// ---------------------------------------------------------------------------
__device__ __forceinline__ unsigned f2tf32(float x) {
    unsigned r;
    asm("cvt.rna.tf32.f32 %0, %1;" : "=r"(r) : "f"(x));
    return r;
}
__device__ __forceinline__ uint4 cvt4(float4 v) {
    uint4 r;
    r.x = f2tf32(v.x); r.y = f2tf32(v.y);
    r.z = f2tf32(v.z); r.w = f2tf32(v.w);
    return r;
}
// D = A(16x8) * B(8x8) + D, tf32 inputs, f32 accum
__device__ __forceinline__ void mma8(float* c, const unsigned* a, const unsigned* b) {
    asm volatile(
        "mma.sync.aligned.m16n8k8.row.col.f32.tf32.tf32.f32 "
        "{%0,%1,%2,%3}, {%4,%5,%6,%7}, {%8,%9}, {%0,%1,%2,%3};\n"
        : "+f"(c[0]), "+f"(c[1]), "+f"(c[2]), "+f"(c[3])
        : "r"(a[0]), "r"(a[1]), "r"(a[2]), "r"(a[3]), "r"(b[0]), "r"(b[1]));
}

// ---------------------------------------------------------------------------
// Tensor-core GEMM: C[M,N] = A[M,K] @ B[K,N] (+bias) (+C if accumulate)
// 128x128 block, 256 threads (8 warps, 2x4), warp tile 64x32, BK=32.
// ---------------------------------------------------------------------------
#define ASP 36     // A smem pitch (k-dim 32 + 4)
#define BSP 136    // B smem pitch (n-dim 128 + 8)

__global__ void __launch_bounds__(256) gemm_t_kernel(
    const float* __restrict__ A, const float* __restrict__ B,
    const float* __restrict__ bias, float* __restrict__ C,
    int M, int N, int K, int accumulate)
{
    __shared__ unsigned As[128 * ASP];
    __shared__ unsigned Bs[32 * BSP];

    const int tid  = threadIdx.x;
    const int warp = tid >> 5;
    const int lane = tid & 31;
    const int m0 = blockIdx.y * 128;
    const int n0 = blockIdx.x * 128;
    const int wm0 = (warp >> 2) * 64;
    const int wn0 = (warp & 3) * 32;

    // staging mapping
    const int am  = tid >> 1;           // 0..127
    const int aks = (tid & 1) * 16;     // 0 or 16
    const int bk  = tid >> 3;           // 0..31
    const int bns = (tid & 7) * 16;     // 0..112

    const float* Ag = A + (size_t)(m0 + am) * K + aks;
    const float* Bg = B + (size_t)bk * N + n0 + bns;

    float acc[4][4][4];
    #pragma unroll
    for (int mt = 0; mt < 4; mt++)
        #pragma unroll
        for (int nt = 0; nt < 4; nt++)
            #pragma unroll
            for (int i = 0; i < 4; i++) acc[mt][nt][i] = 0.0f;

    for (int kt = 0; kt < K; kt += 32) {
        #pragma unroll
        for (int j = 0; j < 4; j++) {
            float4 v = *(const float4*)(Ag + kt + j * 4);
            *(uint4*)&As[am * ASP + aks + j * 4] = cvt4(v);
        }
        #pragma unroll
        for (int j = 0; j < 4; j++) {
            float4 v = *(const float4*)(Bg + (size_t)kt * N + j * 4);
            *(uint4*)&Bs[bk * BSP + bns + j * 4] = cvt4(v);
        }
        __syncthreads();

        #pragma unroll
        for (int ks = 0; ks < 4; ks++) {
            const int kk = ks * 8 + (lane & 3);
            unsigned afr[4][4], bfr[4][2];
            #pragma unroll
            for (int mt = 0; mt < 4; mt++) {
                int r = wm0 + mt * 16 + (lane >> 2);
                afr[mt][0] = As[r * ASP + kk];
                afr[mt][1] = As[(r + 8) * ASP + kk];
                afr[mt][2] = As[r * ASP + kk + 4];
                afr[mt][3] = As[(r + 8) * ASP + kk + 4];
            }
            #pragma unroll
            for (int nt = 0; nt < 4; nt++) {
                int c = wn0 + nt * 8 + (lane >> 2);
                bfr[nt][0] = Bs[kk * BSP + c];
                bfr[nt][1] = Bs[(kk + 4) * BSP + c];
            }
            #pragma unroll
            for (int mt = 0; mt < 4; mt++)
                #pragma unroll
                for (int nt = 0; nt < 4; nt++)
                    mma8(acc[mt][nt], afr[mt], bfr[nt]);
        }
        __syncthreads();
    }

    // Epilogue
    #pragma unroll
    for (int mt = 0; mt < 4; mt++) {
        #pragma unroll
        for (int nt = 0; nt < 4; nt++) {
            int r0 = m0 + wm0 + mt * 16 + (lane >> 2);
            int c0 = n0 + wn0 + nt * 8 + 2 * (lane & 3);
            float v0 = acc[mt][nt][0], v1 = acc[mt][nt][1];
            float v2 = acc[mt][nt][2], v3 = acc[mt][nt][3];
            if (bias) {
                float b0 = bias[c0], b1 = bias[c0 + 1];
                v0 += b0; v1 += b1; v2 += b0; v3 += b1;
            }
            size_t p0 = (size_t)r0 * N + c0;
            size_t p1 = (size_t)(r0 + 8) * N + c0;
            if (accumulate) {
                float2 o0 = *(const float2*)&C[p0];
                float2 o1 = *(const float2*)&C[p1];
                v0 += o0.x; v1 += o0.y; v2 += o1.x; v3 += o1.y;
            }
            float2 w0 = {v0, v1}, w1 = {v2, v3};
            *(float2*)&C[p0] = w0;
            *(float2*)&C[p1] = w1;
        }
    }
}

// ---------------------------------------------------------------------------
// Tensor-core flash attention: block = 128 thr (4 warps), 64 queries/block,
// key tiles of 64. Per warp: 16 query rows. Online softmax on MMA fragments.
// Q,K,V,O in [S, HID] layout, head = blockIdx.y (64 columns).
// ---------------------------------------------------------------------------
#define KSP 72   // K/V/Q smem pitch (64 + 8)
#define PSP 72   // per-warp P patch pitch (64 cols + 8 pad) — must be >= 64!
#define ATTN_SMEM_T (3 * 64 * KSP * 4)

__global__ void __launch_bounds__(128) attn_t_kernel(
    const float* __restrict__ Q, const float* __restrict__ K,
    const float* __restrict__ V, float* __restrict__ O)
{
    extern __shared__ unsigned smem_u[];
    unsigned* Ks = smem_u;                 // [64][KSP]
    unsigned* Vs = Ks + 64 * KSP;          // [64][KSP]
    unsigned* Qs = Vs + 64 * KSP;          // [64][KSP], aliased as Ps later

    const int tid  = threadIdx.x;
    const int warp = tid >> 5;
    const int lane = tid & 31;
    const int hoff = blockIdx.y * HDIM;
    const int q0   = blockIdx.x * 64;

    const int sr  = tid >> 1;           // 0..63
    const int sc0 = (tid & 1) * 32;     // 0 or 32

    // Stage Q tile (tf32)
    #pragma unroll
    for (int j = 0; j < 8; j++) {
        float4 v = *(const float4*)(Q + (size_t)(q0 + sr) * HID + hoff + sc0 + j * 4);
        *(uint4*)&Qs[sr * KSP + sc0 + j * 4] = cvt4(v);
    }
    __syncthreads();

    // Load resident Q fragments (8 k-steps of 8)
    unsigned qa[8][4];
    {
        const int r = warp * 16 + (lane >> 2);
        #pragma unroll
        for (int kt = 0; kt < 8; kt++) {
            int kk = kt * 8 + (lane & 3);
            qa[kt][0] = Qs[r * KSP + kk];
            qa[kt][1] = Qs[(r + 8) * KSP + kk];
            qa[kt][2] = Qs[r * KSP + kk + 4];
            qa[kt][3] = Qs[(r + 8) * KSP + kk + 4];
        }
    }
    __syncthreads();

    float o[8][4];
    #pragma unroll
    for (int nt = 0; nt < 8; nt++)
        #pragma unroll
        for (int i = 0; i < 4; i++) o[nt][i] = 0.0f;
    float mrow0 = -1e30f, mrow1 = -1e30f, lrow0 = 0.0f, lrow1 = 0.0f;

    unsigned* Psw = Qs + warp * (16 * PSP);   // warp-private P patch [16][PSP]

    for (int kt0 = 0; kt0 < S_LEN; kt0 += 64) {
        // Stage K, V tiles (tf32)
        #pragma unroll
        for (int j = 0; j < 8; j++) {
            float4 kv = *(const float4*)(K + (size_t)(kt0 + sr) * HID + hoff + sc0 + j * 4);
            *(uint4*)&Ks[sr * KSP + sc0 + j * 4] = cvt4(kv);
            float4 vv = *(const float4*)(V + (size_t)(kt0 + sr) * HID + hoff + sc0 + j * 4);
            *(uint4*)&Vs[sr * KSP + sc0 + j * 4] = cvt4(vv);
        }
        __syncthreads();

        // S = Q K^T
        float s[8][4];
        #pragma unroll
        for (int nt = 0; nt < 8; nt++)
            #pragma unroll
            for (int i = 0; i < 4; i++) s[nt][i] = 0.0f;

        #pragma unroll
        for (int kk8 = 0; kk8 < 8; kk8++) {
            const int kd = kk8 * 8 + (lane & 3);
            #pragma unroll
            for (int nt = 0; nt < 8; nt++) {
                unsigned b[2];
                int key = nt * 8 + (lane >> 2);
                b[0] = Ks[key * KSP + kd];
                b[1] = Ks[key * KSP + kd + 4];
                mma8(s[nt], qa[kk8], b);
            }
        }

        // Online softmax (rows: r0 = lane/4, r1 = r0+8 within warp's 16)
        float mx0 = -1e30f, mx1 = -1e30f;
        #pragma unroll
        for (int nt = 0; nt < 8; nt++) {
            s[nt][0] *= ATT_SCALE; s[nt][1] *= ATT_SCALE;
            s[nt][2] *= ATT_SCALE; s[nt][3] *= ATT_SCALE;
            mx0 = fmaxf(mx0, fmaxf(s[nt][0], s[nt][1]));
            mx1 = fmaxf(mx1, fmaxf(s[nt][2], s[nt][3]));
        }
        mx0 = fmaxf(mx0, __shfl_xor_sync(0xffffffffu, mx0, 1));
        mx0 = fmaxf(mx0, __shfl_xor_sync(0xffffffffu, mx0, 2));
        mx1 = fmaxf(mx1, __shfl_xor_sync(0xffffffffu, mx1, 1));
        mx1 = fmaxf(mx1, __shfl_xor_sync(0xffffffffu, mx1, 2));

        float mn0 = fmaxf(mrow0, mx0);
        float mn1 = fmaxf(mrow1, mx1);
        float a0 = __expf(mrow0 - mn0);
        float a1 = __expf(mrow1 - mn1);

        const int pr = lane >> 2;
        const int pc = 2 * (lane & 3);
        float rs0 = 0.0f, rs1 = 0.0f;
        #pragma unroll
        for (int nt = 0; nt < 8; nt++) {
            float p0 = __expf(s[nt][0] - mn0);
            float p1 = __expf(s[nt][1] - mn0);
            float p2 = __expf(s[nt][2] - mn1);
            float p3 = __expf(s[nt][3] - mn1);
            rs0 += p0 + p1;
            rs1 += p2 + p3;
            Psw[pr * PSP + nt * 8 + pc]           = f2tf32(p0);
            Psw[pr * PSP + nt * 8 + pc + 1]       = f2tf32(p1);
            Psw[(pr + 8) * PSP + nt * 8 + pc]     = f2tf32(p2);
            Psw[(pr + 8) * PSP + nt * 8 + pc + 1] = f2tf32(p3);
        }
        rs0 += __shfl_xor_sync(0xffffffffu, rs0, 1);
        rs0 += __shfl_xor_sync(0xffffffffu, rs0, 2);
        rs1 += __shfl_xor_sync(0xffffffffu, rs1, 1);
        rs1 += __shfl_xor_sync(0xffffffffu, rs1, 2);

        lrow0 = lrow0 * a0 + rs0;
        lrow1 = lrow1 * a1 + rs1;
        mrow0 = mn0; mrow1 = mn1;
        #pragma unroll
        for (int nt = 0; nt < 8; nt++) {
            o[nt][0] *= a0; o[nt][1] *= a0;
            o[nt][2] *= a1; o[nt][3] *= a1;
        }
        __syncwarp();

        // O += P @ V
        #pragma unroll
        for (int kk8 = 0; kk8 < 8; kk8++) {
            unsigned pa[4];
            const int r  = lane >> 2;
            const int kc = kk8 * 8 + (lane & 3);
            pa[0] = Psw[r * PSP + kc];
            pa[1] = Psw[(r + 8) * PSP + kc];
            pa[2] = Psw[r * PSP + kc + 4];
            pa[3] = Psw[(r + 8) * PSP + kc + 4];
            const int key0 = kk8 * 8 + (lane & 3);
            #pragma unroll
            for (int nt = 0; nt < 8; nt++) {
                unsigned b[2];
                int dc = nt * 8 + (lane >> 2);
                b[0] = Vs[key0 * KSP + dc];
                b[1] = Vs[(key0 + 4) * KSP + dc];
                mma8(o[nt], pa, b);
            }
        }
        __syncthreads();
    }

    // Write O
    float i0 = 1.0f / lrow0;
    float i1 = 1.0f / lrow1;
    int r0 = q0 + warp * 16 + (lane >> 2);
    #pragma unroll
    for (int nt = 0; nt < 8; nt++) {
        int c = hoff + nt * 8 + 2 * (lane & 3);
        float2 v0 = {o[nt][0] * i0, o[nt][1] * i0};
        float2 v1 = {o[nt][2] * i1, o[nt][3] * i1};
        *(float2*)&O[(size_t)r0 * HID + c] = v0;
        *(float2*)&O[(size_t)(r0 + 8) * HID + c] = v1;
    }
}

// ---------------------------------------------------------------------------
// Elementwise kernels
// ---------------------------------------------------------------------------
__global__ void combine_kernel(const float4* __restrict__ a,
                               const float4* __restrict__ b,
                               float4* __restrict__ o, int n4)
{
    int i = blockIdx.x * blockDim.x + threadIdx.x;
    if (i < n4) {
        float4 x = a[i], y = b[i], r;
        r.x = 0.5f * (x.x + y.x); r.y = 0.5f * (x.y + y.y);
        r.z = 0.5f * (x.z + y.z); r.w = 0.5f * (x.w + y.w);
        o[i] = r;
    }
}

__device__ __forceinline__ float sigmoidf_(float x) {
    return 1.0f / (1.0f + __expf(-x));
}

__global__ void gate_kernel(const float4* __restrict__ o,
                            const float4* __restrict__ rec,
                            const float4* __restrict__ gp,
                            float4* __restrict__ out, int n4)
{
    int i = blockIdx.x * blockDim.x + threadIdx.x;
    if (i < n4) {
        float4 ov = o[i], rv = rec[i], gv = gp[i], r;
        r.x = ov.x + sigmoidf_(gv.x) * (rv.x - ov.x);
        r.y = ov.y + sigmoidf_(gv.y) * (rv.y - ov.y);
        r.z = ov.z + sigmoidf_(gv.z) * (rv.z - ov.z);
        r.w = ov.w + sigmoidf_(gv.w) * (rv.w - ov.w);
        out[i] = r;
    }
}

// ---------------------------------------------------------------------------
// Launch
// ---------------------------------------------------------------------------
extern "C" void kernel_launch(void* const* d_in, const int* in_sizes, int n_in,
                              void* d_out, int out_size)
{
    (void)in_sizes; (void)n_in; (void)out_size;

    const float* hs   = (const float*)d_in[0];
    const float* past = (const float*)d_in[1];
    const float* Wq = (const float*)d_in[2];  const float* bq = (const float*)d_in[3];
    const float* Wk = (const float*)d_in[4];  const float* bk = (const float*)d_in[5];
    const float* Wv = (const float*)d_in[6];  const float* bv = (const float*)d_in[7];
    const float* Wo = (const float*)d_in[8];  const float* bo = (const float*)d_in[9];
    const float* Wrq = (const float*)d_in[10]; const float* brq = (const float*)d_in[11];
    const float* Wrk = (const float*)d_in[12]; const float* brk = (const float*)d_in[13];
    const float* Wrv = (const float*)d_in[14]; const float* brv = (const float*)d_in[15];
    const float* Wg = (const float*)d_in[16];  const float* bg = (const float*)d_in[17];

    float *q, *k, *v, *ctx, *out, *rq, *rk, *rv, *rctx, *rec, *gpre;
    cudaGetSymbolAddress((void**)&q,    g_q);
    cudaGetSymbolAddress((void**)&k,    g_k);
    cudaGetSymbolAddress((void**)&v,    g_v);
    cudaGetSymbolAddress((void**)&ctx,  g_ctx);
    cudaGetSymbolAddress((void**)&out,  g_out);
    cudaGetSymbolAddress((void**)&rq,   g_rq);
    cudaGetSymbolAddress((void**)&rk,   g_rk);
    cudaGetSymbolAddress((void**)&rv,   g_rv);
    cudaGetSymbolAddress((void**)&rctx, g_rctx);
    cudaGetSymbolAddress((void**)&rec,  g_rec);
    cudaGetSymbolAddress((void**)&gpre, g_gpre);

    cudaFuncSetAttribute(attn_t_kernel,
                         cudaFuncAttributeMaxDynamicSharedMemorySize, ATTN_SMEM_T);

    dim3 ggrid(HID / 128, S_LEN / 128);       // (8, 16)
    dim3 ggrid2(HID / 128, 2 * S_LEN / 128);  // (8, 32)
    dim3 agrid(S_LEN / 64, NHEAD);            // (32, 16)
    const int n4 = SH / 4;
    const int eblk = 256;
    const int egrd = (n4 + eblk - 1) / eblk;

    // --- self attention ---
    gemm_t_kernel<<<ggrid, 256>>>(hs, Wq, bq, q, S_LEN, HID, HID, 0);
    gemm_t_kernel<<<ggrid, 256>>>(hs, Wk, bk, k, S_LEN, HID, HID, 0);
    gemm_t_kernel<<<ggrid, 256>>>(hs, Wv, bv, v, S_LEN, HID, HID, 0);
    attn_t_kernel<<<agrid, 128, ATTN_SMEM_T>>>(q, k, v, ctx);
    gemm_t_kernel<<<ggrid, 256>>>(ctx, Wo, bo, out, S_LEN, HID, HID, 0);

    // --- recursive attention ---
    gemm_t_kernel<<<ggrid, 256>>>(out, Wrq, brq, rq, S_LEN, HID, HID, 0);
    gemm_t_kernel<<<ggrid2, 256>>>(past, Wrk, brk, rk, 2 * S_LEN, HID, HID, 0);
    gemm_t_kernel<<<ggrid2, 256>>>(past, Wrv, brv, rv, 2 * S_LEN, HID, HID, 0);
    attn_t_kernel<<<agrid, 128, ATTN_SMEM_T>>>(rq, rk,      rv,      rctx);
    attn_t_kernel<<<agrid, 128, ATTN_SMEM_T>>>(rq, rk + SH, rv + SH, rctx + SH);
    combine_kernel<<<egrd, eblk>>>((const float4*)rctx, (const float4*)(rctx + SH),
                                   (float4*)rec, n4);

    // --- gate: gpre = [out, rec] @ Wg + bg (split Wg) ---
    gemm_t_kernel<<<ggrid, 256>>>(out, Wg, bg, gpre, S_LEN, HID, HID, 0);
    gemm_t_kernel<<<ggrid, 256>>>(rec, Wg + (size_t)HID * HID, nullptr, gpre,
                                  S_LEN, HID, HID, 1);

    // --- final blend ---
    gate_kernel<<<egrd, eblk>>>((const float4*)out, (const float4*)rec,
                                (const float4*)gpre, (float4*)d_out, n4);
}

// round 4
// speedup vs baseline: 4.2560x; 1.6630x over previous
#include <cuda_runtime.h>
#include <math.h>
#include <stdint.h>

// Problem constants
#define S_LEN 2048
#define HID   1024
#define NHEAD 16
#define HDIM  64
#define SH    (S_LEN * HID)
#define ATT_SCALE 0.125f   // 1/sqrt(64)

// ---------------------------------------------------------------------------
// Scratch
// ---------------------------------------------------------------------------
__device__ float g_q[SH];
__device__ float g_k[SH];
__device__ float g_v[SH];
__device__ float g_ctx[SH];
__device__ float g_out[SH];
__device__ float g_rq[SH];
__device__ float g_rk[2 * SH];
__device__ float g_rv[2 * SH];
__device__ float g_rctx[2 * SH];
__device__ float g_rec[SH];
__device__ float g_gpre[SH];

// ---------------------------------------------------------------------------
// tf32 helpers
// ---------------------------------------------------------------------------
__device__ __forceinline__ unsigned f2tf32(float x) {
    unsigned r;
    asm("cvt.rna.tf32.f32 %0, %1;" : "=r"(r) : "f"(x));
    return r;
}
__device__ __forceinline__ uint4 cvt4(float4 v) {
    uint4 r;
    r.x = f2tf32(v.x); r.y = f2tf32(v.y);
    r.z = f2tf32(v.z); r.w = f2tf32(v.w);
    return r;
}
__device__ __forceinline__ void mma8(float* c, const unsigned* a, const unsigned* b) {
    asm volatile(
        "mma.sync.aligned.m16n8k8.row.col.f32.tf32.tf32.f32 "
        "{%0,%1,%2,%3}, {%4,%5,%6,%7}, {%8,%9}, {%0,%1,%2,%3};\n"
        : "+f"(c[0]), "+f"(c[1]), "+f"(c[2]), "+f"(c[3])
        : "r"(a[0]), "r"(a[1]), "r"(a[2]), "r"(a[3]), "r"(b[0]), "r"(b[1]));
}

// ---------------------------------------------------------------------------
// GEMM v2: C[M,N] = A[M,K]@B[K,N] (+bias)(+C). 64x128 tile, BK=32, 8 warps,
// warp tile 32x32. A smem interleaved ([0,4,1,5,2,6,3,7] per 8-col group)
// so A-frag pairs load as LDS.64. Register prefetch of next k-stage.
// emit_tf32: round stored C to tf32 (for attention consumers).
// ---------------------------------------------------------------------------
#define GASP 40    // A smem pitch (32 + 8); 40 mod 32 == 8 -> conflict-free
#define GBSP 136   // B smem pitch (128 + 8)

__global__ void __launch_bounds__(256) gemm_t_kernel(
    const float* __restrict__ A, const float* __restrict__ B,
    const float* __restrict__ bias, float* __restrict__ C,
    int M, int N, int K, int accumulate, int emit_tf32)
{
    __shared__ unsigned As[64 * GASP];
    __shared__ unsigned Bs[32 * GBSP];

    const int tid  = threadIdx.x;
    const int warp = tid >> 5;
    const int lane = tid & 31;
    const int m0 = blockIdx.y * 64;
    const int n0 = blockIdx.x * 128;
    const int wm0 = (warp >> 2) * 32;
    const int wn0 = (warp & 3) * 32;

    // staging mapping
    const int arow = tid >> 2;         // 0..63
    const int ah   = tid & 3;          // group index 0..3 (8 cols each)
    const int brow = tid >> 3;         // 0..31
    const int bc   = tid & 7;          // 0..7

    const float* Ag = A + (size_t)(m0 + arow) * K + ah * 8;
    const float* Bg = B + (size_t)brow * N + n0 + bc * 4;

    float acc[2][4][4];
    #pragma unroll
    for (int mt = 0; mt < 2; mt++)
        #pragma unroll
        for (int nt = 0; nt < 4; nt++)
            #pragma unroll
            for (int i = 0; i < 4; i++) acc[mt][nt][i] = 0.0f;

    // prefetch stage 0
    float4 ra0 = *(const float4*)(Ag);
    float4 ra1 = *(const float4*)(Ag + 4);
    float4 rb[4];
    #pragma unroll
    for (int j = 0; j < 4; j++) rb[j] = *(const float4*)(Bg + j * 32);

    for (int kt = 0; kt < K; kt += 32) {
        // store current stage (cvt + interleave A)
        {
            uint4 a0 = cvt4(ra0), a1 = cvt4(ra1);
            uint4 w0 = {a0.x, a1.x, a0.y, a1.y};
            uint4 w1 = {a0.z, a1.z, a0.w, a1.w};
            *(uint4*)&As[arow * GASP + ah * 8]     = w0;
            *(uint4*)&As[arow * GASP + ah * 8 + 4] = w1;
            #pragma unroll
            for (int j = 0; j < 4; j++)
                *(uint4*)&Bs[brow * GBSP + bc * 4 + j * 32] = cvt4(rb[j]);
        }
        __syncthreads();

        // prefetch next stage
        if (kt + 32 < K) {
            ra0 = *(const float4*)(Ag + kt + 32);
            ra1 = *(const float4*)(Ag + kt + 36);
            #pragma unroll
            for (int j = 0; j < 4; j++)
                rb[j] = *(const float4*)(Bg + (size_t)(kt + 32) * N + j * 32);
        }

        #pragma unroll
        for (int ks = 0; ks < 4; ks++) {
            const int c2 = 2 * (lane & 3);
            unsigned afr[2][4], bfr[4][2];
            #pragma unroll
            for (int mt = 0; mt < 2; mt++) {
                int r = wm0 + mt * 16 + (lane >> 2);
                uint2 x = *(uint2*)&As[r * GASP + ks * 8 + c2];
                uint2 y = *(uint2*)&As[(r + 8) * GASP + ks * 8 + c2];
                afr[mt][0] = x.x; afr[mt][1] = y.x;
                afr[mt][2] = x.y; afr[mt][3] = y.y;
            }
            const int kk = ks * 8 + (lane & 3);
            #pragma unroll
            for (int nt = 0; nt < 4; nt++) {
                int c = wn0 + nt * 8 + (lane >> 2);
                bfr[nt][0] = Bs[kk * GBSP + c];
                bfr[nt][1] = Bs[(kk + 4) * GBSP + c];
            }
            #pragma unroll
            for (int mt = 0; mt < 2; mt++)
                #pragma unroll
                for (int nt = 0; nt < 4; nt++)
                    mma8(acc[mt][nt], afr[mt], bfr[nt]);
        }
        __syncthreads();
    }

    // Epilogue
    #pragma unroll
    for (int mt = 0; mt < 2; mt++) {
        #pragma unroll
        for (int nt = 0; nt < 4; nt++) {
            int r0 = m0 + wm0 + mt * 16 + (lane >> 2);
            int c0 = n0 + wn0 + nt * 8 + 2 * (lane & 3);
            float v0 = acc[mt][nt][0], v1 = acc[mt][nt][1];
            float v2 = acc[mt][nt][2], v3 = acc[mt][nt][3];
            if (bias) {
                float b0 = bias[c0], b1 = bias[c0 + 1];
                v0 += b0; v1 += b1; v2 += b0; v3 += b1;
            }
            size_t p0 = (size_t)r0 * N + c0;
            size_t p1 = (size_t)(r0 + 8) * N + c0;
            if (accumulate) {
                float2 o0 = *(const float2*)&C[p0];
                float2 o1 = *(const float2*)&C[p1];
                v0 += o0.x; v1 += o0.y; v2 += o1.x; v3 += o1.y;
            }
            if (emit_tf32) {
                v0 = __uint_as_float(f2tf32(v0));
                v1 = __uint_as_float(f2tf32(v1));
                v2 = __uint_as_float(f2tf32(v2));
                v3 = __uint_as_float(f2tf32(v3));
            }
            float2 w0 = {v0, v1}, w1 = {v2, v3};
            *(float2*)&C[p0] = w0;
            *(float2*)&C[p1] = w1;
        }
    }
}

// ---------------------------------------------------------------------------
// Flash attention v2: 256 thr (8 warps), 128 queries/block, key tiles of 64.
// Inputs hold tf32 bit patterns (pre-rounded by GEMM epilogue) -> staging is
// a pure bit copy. Q and K tiles stored interleaved for LDS.64 frag loads.
// P stored interleaved in the (reused) Q smem region, warp-private.
// ---------------------------------------------------------------------------
#define KSP 72   // pitch (64 + 8); 72 mod 32 == 8 -> conflict-free phases
#define ATTN_SMEM_T ((128 + 64 + 64) * KSP * 4)

__global__ void __launch_bounds__(256) attn_t_kernel(
    const float* __restrict__ Q, const float* __restrict__ K,
    const float* __restrict__ V, float* __restrict__ O)
{
    extern __shared__ unsigned smem_u[];
    unsigned* Qs = smem_u;                 // [128][KSP] (interleaved); P later
    unsigned* Ks = Qs + 128 * KSP;         // [64][KSP]  (interleaved)
    unsigned* Vs = Ks + 64 * KSP;          // [64][KSP]  (natural)

    const int tid  = threadIdx.x;
    const int warp = tid >> 5;
    const int lane = tid & 31;
    const int hoff = blockIdx.y * HDIM;
    const int q0   = blockIdx.x * 128;

    // --- Stage Q (interleaved), 128 rows x 64 cols ---
    {
        const int row  = tid >> 1;          // 0..127
        const int half = tid & 1;           // 0/1 -> groups [4h, 4h+4)
        const uint4* Qg = (const uint4*)(Q + (size_t)(q0 + row) * HID + hoff);
        #pragma unroll
        for (int gg = 0; gg < 4; gg++) {
            int g = half * 4 + gg;
            uint4 u0 = Qg[g * 2];
            uint4 u1 = Qg[g * 2 + 1];
            uint4 w0 = {u0.x, u1.x, u0.y, u1.y};
            uint4 w1 = {u0.z, u1.z, u0.w, u1.w};
            *(uint4*)&Qs[row * KSP + g * 8]     = w0;
            *(uint4*)&Qs[row * KSP + g * 8 + 4] = w1;
        }
    }
    __syncthreads();

    // --- Resident Q fragments ---
    unsigned qa[8][4];
    {
        const int r  = warp * 16 + (lane >> 2);
        const int c2 = 2 * (lane & 3);
        #pragma unroll
        for (int kt = 0; kt < 8; kt++) {
            uint2 x = *(uint2*)&Qs[r * KSP + kt * 8 + c2];
            uint2 y = *(uint2*)&Qs[(r + 8) * KSP + kt * 8 + c2];
            qa[kt][0] = x.x; qa[kt][1] = y.x;
            qa[kt][2] = x.y; qa[kt][3] = y.y;
        }
    }

    float o[8][4];
    #pragma unroll
    for (int nt = 0; nt < 8; nt++)
        #pragma unroll
        for (int i = 0; i < 4; i++) o[nt][i] = 0.0f;
    float mrow0 = -1e30f, mrow1 = -1e30f, lrow0 = 0.0f, lrow1 = 0.0f;

    unsigned* Pw = Qs + warp * (16 * KSP);   // warp-private [16][KSP]

    // staging mapping for K/V: 64 rows, 4 threads/row
    const int srow = tid >> 2;          // 0..63
    const int sq   = tid & 3;           // quarter: 16 cols

    for (int kt0 = 0; kt0 < S_LEN; kt0 += 64) {
        // --- Stage K (interleaved) + V (natural), bit copy ---
        {
            const uint4* Kg = (const uint4*)(K + (size_t)(kt0 + srow) * HID + hoff);
            const uint4* Vg = (const uint4*)(V + (size_t)(kt0 + srow) * HID + hoff);
            #pragma unroll
            for (int gg = 0; gg < 2; gg++) {
                int g = sq * 2 + gg;
                uint4 u0 = Kg[g * 2];
                uint4 u1 = Kg[g * 2 + 1];
                uint4 w0 = {u0.x, u1.x, u0.y, u1.y};
                uint4 w1 = {u0.z, u1.z, u0.w, u1.w};
                *(uint4*)&Ks[srow * KSP + g * 8]     = w0;
                *(uint4*)&Ks[srow * KSP + g * 8 + 4] = w1;
            }
            #pragma unroll
            for (int j = 0; j < 4; j++)
                *(uint4*)&Vs[srow * KSP + sq * 16 + j * 4] = Vg[sq * 4 + j];
        }
        __syncthreads();

        // --- S = Q K^T ---
        float s[8][4];
        #pragma unroll
        for (int nt = 0; nt < 8; nt++)
            #pragma unroll
            for (int i = 0; i < 4; i++) s[nt][i] = 0.0f;

        {
            const int c2 = 2 * (lane & 3);
            const int kr = lane >> 2;
            #pragma unroll
            for (int g = 0; g < 8; g++) {
                #pragma unroll
                for (int nt = 0; nt < 8; nt++) {
                    uint2 b = *(uint2*)&Ks[(nt * 8 + kr) * KSP + g * 8 + c2];
                    mma8(s[nt], qa[g], &b.x);
                }
            }
        }

        // --- Online softmax ---
        float mx0 = -1e30f, mx1 = -1e30f;
        #pragma unroll
        for (int nt = 0; nt < 8; nt++) {
            s[nt][0] *= ATT_SCALE; s[nt][1] *= ATT_SCALE;
            s[nt][2] *= ATT_SCALE; s[nt][3] *= ATT_SCALE;
            mx0 = fmaxf(mx0, fmaxf(s[nt][0], s[nt][1]));
            mx1 = fmaxf(mx1, fmaxf(s[nt][2], s[nt][3]));
        }
        mx0 = fmaxf(mx0, __shfl_xor_sync(0xffffffffu, mx0, 1));
        mx0 = fmaxf(mx0, __shfl_xor_sync(0xffffffffu, mx0, 2));
        mx1 = fmaxf(mx1, __shfl_xor_sync(0xffffffffu, mx1, 1));
        mx1 = fmaxf(mx1, __shfl_xor_sync(0xffffffffu, mx1, 2));

        float mn0 = fmaxf(mrow0, mx0);
        float mn1 = fmaxf(mrow1, mx1);
        float a0 = __expf(mrow0 - mn0);
        float a1 = __expf(mrow1 - mn1);

        // P store (interleaved positions), warp-private region
        {
            const int pr = lane >> 2;
            const int j  = lane & 3;
            const int ie = (j < 2) ? 4 * j : 4 * j - 7;   // pos of col 2j
            const int io = (j < 2) ? 4 * j + 2 : 4 * j - 5; // pos of col 2j+1
            float rs0 = 0.0f, rs1 = 0.0f;
            #pragma unroll
            for (int nt = 0; nt < 8; nt++) {
                float p0 = __expf(s[nt][0] - mn0);
                float p1 = __expf(s[nt][1] - mn0);
                float p2 = __expf(s[nt][2] - mn1);
                float p3 = __expf(s[nt][3] - mn1);
                rs0 += p0 + p1;
                rs1 += p2 + p3;
                Pw[pr * KSP + nt * 8 + ie]       = f2tf32(p0);
                Pw[pr * KSP + nt * 8 + io]       = f2tf32(p1);
                Pw[(pr + 8) * KSP + nt * 8 + ie] = f2tf32(p2);
                Pw[(pr + 8) * KSP + nt * 8 + io] = f2tf32(p3);
            }
            rs0 += __shfl_xor_sync(0xffffffffu, rs0, 1);
            rs0 += __shfl_xor_sync(0xffffffffu, rs0, 2);
            rs1 += __shfl_xor_sync(0xffffffffu, rs1, 1);
            rs1 += __shfl_xor_sync(0xffffffffu, rs1, 2);

            lrow0 = lrow0 * a0 + rs0;
            lrow1 = lrow1 * a1 + rs1;
            mrow0 = mn0; mrow1 = mn1;
        }
        #pragma unroll
        for (int nt = 0; nt < 8; nt++) {
            o[nt][0] *= a0; o[nt][1] *= a0;
            o[nt][2] *= a1; o[nt][3] *= a1;
        }
        __syncwarp();

        // --- O += P @ V ---
        {
            const int pr = lane >> 2;
            const int c2 = 2 * (lane & 3);
            const int vc0 = lane >> 2;
            #pragma unroll
            for (int g = 0; g < 8; g++) {
                unsigned pa[4];
                uint2 x = *(uint2*)&Pw[pr * KSP + g * 8 + c2];
                uint2 y = *(uint2*)&Pw[(pr + 8) * KSP + g * 8 + c2];
                pa[0] = x.x; pa[1] = y.x; pa[2] = x.y; pa[3] = y.y;
                const int kr = g * 8 + (lane & 3);
                #pragma unroll
                for (int nt = 0; nt < 8; nt++) {
                    unsigned b[2];
                    int dc = nt * 8 + vc0;
                    b[0] = Vs[kr * KSP + dc];
                    b[1] = Vs[(kr + 4) * KSP + dc];
                    mma8(o[nt], pa, b);
                }
            }
        }
        __syncthreads();
    }

    // --- Write O ---
    float i0 = 1.0f / lrow0;
    float i1 = 1.0f / lrow1;
    int r0 = q0 + warp * 16 + (lane >> 2);
    #pragma unroll
    for (int nt = 0; nt < 8; nt++) {
        int c = hoff + nt * 8 + 2 * (lane & 3);
        float2 v0 = {o[nt][0] * i0, o[nt][1] * i0};
        float2 v1 = {o[nt][2] * i1, o[nt][3] * i1};
        *(float2*)&O[(size_t)r0 * HID + c] = v0;
        *(float2*)&O[(size_t)(r0 + 8) * HID + c] = v1;
    }
}

// ---------------------------------------------------------------------------
// Elementwise kernels
// ---------------------------------------------------------------------------
__global__ void combine_kernel(const float4* __restrict__ a,
                               const float4* __restrict__ b,
                               float4* __restrict__ o, int n4)
{
    int i = blockIdx.x * blockDim.x + threadIdx.x;
    if (i < n4) {
        float4 x = a[i], y = b[i], r;
        r.x = 0.5f * (x.x + y.x); r.y = 0.5f * (x.y + y.y);
        r.z = 0.5f * (x.z + y.z); r.w = 0.5f * (x.w + y.w);
        o[i] = r;
    }
}

__device__ __forceinline__ float sigmoidf_(float x) {
    return 1.0f / (1.0f + __expf(-x));
}

__global__ void gate_kernel(const float4* __restrict__ o,
                            const float4* __restrict__ rec,
                            const float4* __restrict__ gp,
                            float4* __restrict__ out, int n4)
{
    int i = blockIdx.x * blockDim.x + threadIdx.x;
    if (i < n4) {
        float4 ov = o[i], rv = rec[i], gv = gp[i], r;
        r.x = ov.x + sigmoidf_(gv.x) * (rv.x - ov.x);
        r.y = ov.y + sigmoidf_(gv.y) * (rv.y - ov.y);
        r.z = ov.z + sigmoidf_(gv.z) * (rv.z - ov.z);
        r.w = ov.w + sigmoidf_(gv.w) * (rv.w - ov.w);
        out[i] = r;
    }
}

// ---------------------------------------------------------------------------
// Launch
// ---------------------------------------------------------------------------
extern "C" void kernel_launch(void* const* d_in, const int* in_sizes, int n_in,
                              void* d_out, int out_size)
{
    (void)in_sizes; (void)n_in; (void)out_size;

    const float* hs   = (const float*)d_in[0];
    const float* past = (const float*)d_in[1];
    const float* Wq = (const float*)d_in[2];  const float* bq = (const float*)d_in[3];
    const float* Wk = (const float*)d_in[4];  const float* bk = (const float*)d_in[5];
    const float* Wv = (const float*)d_in[6];  const float* bv = (const float*)d_in[7];
    const float* Wo = (const float*)d_in[8];  const float* bo = (const float*)d_in[9];
    const float* Wrq = (const float*)d_in[10]; const float* brq = (const float*)d_in[11];
    const float* Wrk = (const float*)d_in[12]; const float* brk = (const float*)d_in[13];
    const float* Wrv = (const float*)d_in[14]; const float* brv = (const float*)d_in[15];
    const float* Wg = (const float*)d_in[16];  const float* bg = (const float*)d_in[17];

    float *q, *k, *v, *ctx, *out, *rq, *rk, *rv, *rctx, *rec, *gpre;
    cudaGetSymbolAddress((void**)&q,    g_q);
    cudaGetSymbolAddress((void**)&k,    g_k);
    cudaGetSymbolAddress((void**)&v,    g_v);
    cudaGetSymbolAddress((void**)&ctx,  g_ctx);
    cudaGetSymbolAddress((void**)&out,  g_out);
    cudaGetSymbolAddress((void**)&rq,   g_rq);
    cudaGetSymbolAddress((void**)&rk,   g_rk);
    cudaGetSymbolAddress((void**)&rv,   g_rv);
    cudaGetSymbolAddress((void**)&rctx, g_rctx);
    cudaGetSymbolAddress((void**)&rec,  g_rec);
    cudaGetSymbolAddress((void**)&gpre, g_gpre);

    cudaFuncSetAttribute(attn_t_kernel,
                         cudaFuncAttributeMaxDynamicSharedMemorySize, ATTN_SMEM_T);

    dim3 ggrid(HID / 128, S_LEN / 64);        // (8, 32)
    dim3 ggrid2(HID / 128, 2 * S_LEN / 64);   // (8, 64)
    dim3 agrid(S_LEN / 128, NHEAD);           // (16, 16)
    const int n4 = SH / 4;
    const int eblk = 256;
    const int egrd = (n4 + eblk - 1) / eblk;

    // --- self attention ---
    gemm_t_kernel<<<ggrid, 256>>>(hs, Wq, bq, q, S_LEN, HID, HID, 0, 1);
    gemm_t_kernel<<<ggrid, 256>>>(hs, Wk, bk, k, S_LEN, HID, HID, 0, 1);
    gemm_t_kernel<<<ggrid, 256>>>(hs, Wv, bv, v, S_LEN, HID, HID, 0, 1);
    attn_t_kernel<<<agrid, 256, ATTN_SMEM_T>>>(q, k, v, ctx);
    gemm_t_kernel<<<ggrid, 256>>>(ctx, Wo, bo, out, S_LEN, HID, HID, 0, 0);

    // --- recursive attention ---
    gemm_t_kernel<<<ggrid, 256>>>(out, Wrq, brq, rq, S_LEN, HID, HID, 0, 1);
    gemm_t_kernel<<<ggrid2, 256>>>(past, Wrk, brk, rk, 2 * S_LEN, HID, HID, 0, 1);
    gemm_t_kernel<<<ggrid2, 256>>>(past, Wrv, brv, rv, 2 * S_LEN, HID, HID, 0, 1);
    attn_t_kernel<<<agrid, 256, ATTN_SMEM_T>>>(rq, rk,      rv,      rctx);
    attn_t_kernel<<<agrid, 256, ATTN_SMEM_T>>>(rq, rk + SH, rv + SH, rctx + SH);
    combine_kernel<<<egrd, eblk>>>((const float4*)rctx, (const float4*)(rctx + SH),
                                   (float4*)rec, n4);

    // --- gate: gpre = [out, rec] @ Wg + bg (split Wg) ---
    gemm_t_kernel<<<ggrid, 256>>>(out, Wg, bg, gpre, S_LEN, HID, HID, 0, 0);
    gemm_t_kernel<<<ggrid, 256>>>(rec, Wg + (size_t)HID * HID, nullptr, gpre,
                                  S_LEN, HID, HID, 1, 0);

    // --- final blend ---
    gate_kernel<<<egrd, eblk>>>((const float4*)out, (const float4*)rec,
                                (const float4*)gpre, (float4*)d_out, n4);
}

// round 5
// speedup vs baseline: 4.5330x; 1.0651x over previous
#include <cuda_runtime.h>
#include <math.h>
#include <stdint.h>

// Problem constants
#define S_LEN 2048
#define HID   1024
#define NHEAD 16
#define HDIM  64
#define SH    (S_LEN * HID)
#define SCL2  0.1803368801111204f   // (1/sqrt(64)) * log2(e)
#define LOG2E 1.4426950408889634f

// ---------------------------------------------------------------------------
// Scratch
// ---------------------------------------------------------------------------
__device__ float g_q[SH];
__device__ float g_k[SH];
__device__ float g_v[SH];
__device__ float g_ctx[SH];
__device__ float g_out[SH];
__device__ float g_rq[SH];
__device__ float g_rk[2 * SH];
__device__ float g_rv[2 * SH];
__device__ float g_rctx[2 * SH];
__device__ float g_rec[SH];

// ---------------------------------------------------------------------------
// helpers
// ---------------------------------------------------------------------------
__device__ __forceinline__ unsigned f2tf32(float x) {
    unsigned r;
    asm("cvt.rna.tf32.f32 %0, %1;" : "=r"(r) : "f"(x));
    return r;
}
__device__ __forceinline__ uint4 cvt4(float4 v) {
    uint4 r;
    r.x = f2tf32(v.x); r.y = f2tf32(v.y);
    r.z = f2tf32(v.z); r.w = f2tf32(v.w);
    return r;
}
__device__ __forceinline__ void mma8(float* c, const unsigned* a, const unsigned* b) {
    asm volatile(
        "mma.sync.aligned.m16n8k8.row.col.f32.tf32.tf32.f32 "
        "{%0,%1,%2,%3}, {%4,%5,%6,%7}, {%8,%9}, {%0,%1,%2,%3};\n"
        : "+f"(c[0]), "+f"(c[1]), "+f"(c[2]), "+f"(c[3])
        : "r"(a[0]), "r"(a[1]), "r"(a[2]), "r"(a[3]), "r"(b[0]), "r"(b[1]));
}
__device__ __forceinline__ void ldsm4(unsigned &r0, unsigned &r1,
                                      unsigned &r2, unsigned &r3, unsigned a) {
    asm volatile("ldmatrix.sync.aligned.m8n8.x4.shared.b16 {%0,%1,%2,%3}, [%4];"
        : "=r"(r0), "=r"(r1), "=r"(r2), "=r"(r3) : "r"(a));
}
__device__ __forceinline__ unsigned sptr(const void* p) {
    return (unsigned)__cvta_generic_to_shared(p);
}
__device__ __forceinline__ float ex2f(float x) {
    float y; asm("ex2.approx.ftz.f32 %0, %1;" : "=f"(y) : "f"(x)); return y;
}
#define CP_ASYNC16(dst, src) \
    asm volatile("cp.async.cg.shared.global [%0], [%1], 16;" :: "r"(dst), "l"(src) : "memory")
#define CP_COMMIT() asm volatile("cp.async.commit_group;" ::: "memory")
#define CP_WAIT0()  asm volatile("cp.async.wait_group 0;" ::: "memory")

// ---------------------------------------------------------------------------
// Batched projection GEMM: C[z] = A @ B[z] + bias[z]; 64x128 tile, BK=32,
// 8 warps, warp tile 32x32. z = blockIdx.z selects weight/output.
// ---------------------------------------------------------------------------
#define GASP 40
#define GBSP 136

struct GB3 {
    const float* B[3];
    const float* bias[3];
    float* C[3];
};

__global__ void __launch_bounds__(256) gemm_b3_kernel(
    const float* __restrict__ A, GB3 gb, int M, int N, int K, int emit_tf32)
{
    __shared__ unsigned As[64 * GASP];
    __shared__ unsigned Bs[32 * GBSP];

    const float* __restrict__ B    = gb.B[blockIdx.z];
    const float* __restrict__ bias = gb.bias[blockIdx.z];
    float* __restrict__ C          = gb.C[blockIdx.z];

    const int tid  = threadIdx.x;
    const int warp = tid >> 5;
    const int lane = tid & 31;
    const int m0 = blockIdx.y * 64;
    const int n0 = blockIdx.x * 128;
    const int wm0 = (warp >> 2) * 32;
    const int wn0 = (warp & 3) * 32;

    const int arow = tid >> 2;
    const int ah   = tid & 3;
    const int brow = tid >> 3;
    const int bc   = tid & 7;

    const float* Ag = A + (size_t)(m0 + arow) * K + ah * 8;
    const float* Bg = B + (size_t)brow * N + n0 + bc * 4;

    float acc[2][4][4];
    #pragma unroll
    for (int mt = 0; mt < 2; mt++)
        #pragma unroll
        for (int nt = 0; nt < 4; nt++)
            #pragma unroll
            for (int i = 0; i < 4; i++) acc[mt][nt][i] = 0.0f;

    float4 ra0 = *(const float4*)(Ag);
    float4 ra1 = *(const float4*)(Ag + 4);
    float4 rb[4];
    #pragma unroll
    for (int j = 0; j < 4; j++) rb[j] = *(const float4*)(Bg + j * 32);

    for (int kt = 0; kt < K; kt += 32) {
        {
            uint4 a0 = cvt4(ra0), a1 = cvt4(ra1);
            uint4 w0 = {a0.x, a1.x, a0.y, a1.y};
            uint4 w1 = {a0.z, a1.z, a0.w, a1.w};
            *(uint4*)&As[arow * GASP + ah * 8]     = w0;
            *(uint4*)&As[arow * GASP + ah * 8 + 4] = w1;
            #pragma unroll
            for (int j = 0; j < 4; j++)
                *(uint4*)&Bs[brow * GBSP + bc * 4 + j * 32] = cvt4(rb[j]);
        }
        __syncthreads();

        if (kt + 32 < K) {
            ra0 = *(const float4*)(Ag + kt + 32);
            ra1 = *(const float4*)(Ag + kt + 36);
            #pragma unroll
            for (int j = 0; j < 4; j++)
                rb[j] = *(const float4*)(Bg + (size_t)(kt + 32) * N + j * 32);
        }

        #pragma unroll
        for (int ks = 0; ks < 4; ks++) {
            const int c2 = 2 * (lane & 3);
            unsigned afr[2][4], bfr[4][2];
            #pragma unroll
            for (int mt = 0; mt < 2; mt++) {
                int r = wm0 + mt * 16 + (lane >> 2);
                uint2 x = *(uint2*)&As[r * GASP + ks * 8 + c2];
                uint2 y = *(uint2*)&As[(r + 8) * GASP + ks * 8 + c2];
                afr[mt][0] = x.x; afr[mt][1] = y.x;
                afr[mt][2] = x.y; afr[mt][3] = y.y;
            }
            const int kk = ks * 8 + (lane & 3);
            #pragma unroll
            for (int nt = 0; nt < 4; nt++) {
                int c = wn0 + nt * 8 + (lane >> 2);
                bfr[nt][0] = Bs[kk * GBSP + c];
                bfr[nt][1] = Bs[(kk + 4) * GBSP + c];
            }
            #pragma unroll
            for (int mt = 0; mt < 2; mt++)
                #pragma unroll
                for (int nt = 0; nt < 4; nt++)
                    mma8(acc[mt][nt], afr[mt], bfr[nt]);
        }
        __syncthreads();
    }

    #pragma unroll
    for (int mt = 0; mt < 2; mt++) {
        #pragma unroll
        for (int nt = 0; nt < 4; nt++) {
            int r0 = m0 + wm0 + mt * 16 + (lane >> 2);
            int c0 = n0 + wn0 + nt * 8 + 2 * (lane & 3);
            float b0 = bias[c0], b1 = bias[c0 + 1];
            float v0 = acc[mt][nt][0] + b0, v1 = acc[mt][nt][1] + b1;
            float v2 = acc[mt][nt][2] + b0, v3 = acc[mt][nt][3] + b1;
            if (emit_tf32) {
                v0 = __uint_as_float(f2tf32(v0));
                v1 = __uint_as_float(f2tf32(v1));
                v2 = __uint_as_float(f2tf32(v2));
                v3 = __uint_as_float(f2tf32(v3));
            }
            float2 w0 = {v0, v1}, w1 = {v2, v3};
            *(float2*)&C[(size_t)r0 * N + c0]       = w0;
            *(float2*)&C[(size_t)(r0 + 8) * N + c0] = w1;
        }
    }
}

// ---------------------------------------------------------------------------
// Fused gate GEMM: gpre = [out|rec] @ Wg + bg (K=2048), then
// dst = out + sigmoid(gpre) * (rec - out). Writes d_out directly.
// ---------------------------------------------------------------------------
__global__ void __launch_bounds__(256) gemm_gate_kernel(
    const float* __restrict__ Aout, const float* __restrict__ Arec,
    const float* __restrict__ B, const float* __restrict__ bias,
    float* __restrict__ dst, int M, int N)
{
    __shared__ unsigned As[64 * GASP];
    __shared__ unsigned Bs[32 * GBSP];

    const int tid  = threadIdx.x;
    const int warp = tid >> 5;
    const int lane = tid & 31;
    const int m0 = blockIdx.y * 64;
    const int n0 = blockIdx.x * 128;
    const int wm0 = (warp >> 2) * 32;
    const int wn0 = (warp & 3) * 32;

    const int arow = tid >> 2;
    const int ah   = tid & 3;
    const int brow = tid >> 3;
    const int bc   = tid & 7;

    const size_t aoff = (size_t)(m0 + arow) * HID + ah * 8;
    const float* Bg = B + (size_t)brow * N + n0 + bc * 4;

    float acc[2][4][4];
    #pragma unroll
    for (int mt = 0; mt < 2; mt++)
        #pragma unroll
        for (int nt = 0; nt < 4; nt++)
            #pragma unroll
            for (int i = 0; i < 4; i++) acc[mt][nt][i] = 0.0f;

    float4 ra0 = *(const float4*)(Aout + aoff);
    float4 ra1 = *(const float4*)(Aout + aoff + 4);
    float4 rb[4];
    #pragma unroll
    for (int j = 0; j < 4; j++) rb[j] = *(const float4*)(Bg + j * 32);

    for (int kt = 0; kt < 2 * HID; kt += 32) {
        {
            uint4 a0 = cvt4(ra0), a1 = cvt4(ra1);
            uint4 w0 = {a0.x, a1.x, a0.y, a1.y};
            uint4 w1 = {a0.z, a1.z, a0.w, a1.w};
            *(uint4*)&As[arow * GASP + ah * 8]     = w0;
            *(uint4*)&As[arow * GASP + ah * 8 + 4] = w1;
            #pragma unroll
            for (int j = 0; j < 4; j++)
                *(uint4*)&Bs[brow * GBSP + bc * 4 + j * 32] = cvt4(rb[j]);
        }
        __syncthreads();

        if (kt + 32 < 2 * HID) {
            int kn = kt + 32;
            const float* Asrc = (kn < HID) ? Aout : Arec;
            ra0 = *(const float4*)(Asrc + aoff + (kn & (HID - 1)));
            ra1 = *(const float4*)(Asrc + aoff + (kn & (HID - 1)) + 4);
            #pragma unroll
            for (int j = 0; j < 4; j++)
                rb[j] = *(const float4*)(Bg + (size_t)kn * N + j * 32);
        }

        #pragma unroll
        for (int ks = 0; ks < 4; ks++) {
            const int c2 = 2 * (lane & 3);
            unsigned afr[2][4], bfr[4][2];
            #pragma unroll
            for (int mt = 0; mt < 2; mt++) {
                int r = wm0 + mt * 16 + (lane >> 2);
                uint2 x = *(uint2*)&As[r * GASP + ks * 8 + c2];
                uint2 y = *(uint2*)&As[(r + 8) * GASP + ks * 8 + c2];
                afr[mt][0] = x.x; afr[mt][1] = y.x;
                afr[mt][2] = x.y; afr[mt][3] = y.y;
            }
            const int kk = ks * 8 + (lane & 3);
            #pragma unroll
            for (int nt = 0; nt < 4; nt++) {
                int c = wn0 + nt * 8 + (lane >> 2);
                bfr[nt][0] = Bs[kk * GBSP + c];
                bfr[nt][1] = Bs[(kk + 4) * GBSP + c];
            }
            #pragma unroll
            for (int mt = 0; mt < 2; mt++)
                #pragma unroll
                for (int nt = 0; nt < 4; nt++)
                    mma8(acc[mt][nt], afr[mt], bfr[nt]);
        }
        __syncthreads();
    }

    #pragma unroll
    for (int mt = 0; mt < 2; mt++) {
        #pragma unroll
        for (int nt = 0; nt < 4; nt++) {
            int r0 = m0 + wm0 + mt * 16 + (lane >> 2);
            int c0 = n0 + wn0 + nt * 8 + 2 * (lane & 3);
            float b0 = bias[c0], b1 = bias[c0 + 1];
            float gp0 = acc[mt][nt][0] + b0, gp1 = acc[mt][nt][1] + b1;
            float gp2 = acc[mt][nt][2] + b0, gp3 = acc[mt][nt][3] + b1;
            size_t p0 = (size_t)r0 * N + c0;
            size_t p1 = (size_t)(r0 + 8) * N + c0;
            float2 o0 = *(const float2*)&Aout[p0];
            float2 o1 = *(const float2*)&Aout[p1];
            float2 rc0 = *(const float2*)&Arec[p0];
            float2 rc1 = *(const float2*)&Arec[p1];
            float g0 = 1.0f / (1.0f + ex2f(-gp0 * LOG2E));
            float g1 = 1.0f / (1.0f + ex2f(-gp1 * LOG2E));
            float g2 = 1.0f / (1.0f + ex2f(-gp2 * LOG2E));
            float g3 = 1.0f / (1.0f + ex2f(-gp3 * LOG2E));
            float2 w0 = {o0.x + g0 * (rc0.x - o0.x), o0.y + g1 * (rc0.y - o0.y)};
            float2 w1 = {o1.x + g2 * (rc1.x - o1.x), o1.y + g3 * (rc1.y - o1.y)};
            *(float2*)&dst[p0] = w0;
            *(float2*)&dst[p1] = w1;
        }
    }
}

// ---------------------------------------------------------------------------
// Flash attention v3: 256 thr (8 warps), 128 queries/block, key tiles of 64.
// Inputs pre-rounded to tf32. All MMA fragments via ldmatrix.x4 on natural
// layouts. K double-buffered via cp.async; V transposed to d-major Vt.
// Q smem region reused as P region (warp w owns rows [16w, 16w+16)).
// ---------------------------------------------------------------------------
#define PW 68
#define ATTN_WORDS ((128 + 2 * 64 + 64) * PW)   // QP + K0 + K1 + Vt
#define ATTN_SMEM  (ATTN_WORDS * 4)

__global__ void __launch_bounds__(256, 2) attn_t_kernel(
    const float* __restrict__ Q, const float* __restrict__ K,
    const float* __restrict__ V, float* __restrict__ O)
{
    extern __shared__ unsigned sm[];
    unsigned* QP = sm;                       // [128][PW] Q then P
    unsigned* KB = sm + 128 * PW;            // 2 x [64][PW]
    unsigned* VT = sm + (128 + 128) * PW;    // [64][PW] d-major

    const int tid  = threadIdx.x;
    const int warp = tid >> 5;
    const int lane = tid & 31;
    const int hoff = blockIdx.y * HDIM;
    const int q0   = blockIdx.x * 128;

    // lane decompositions for ldmatrix addressing
    const int lr  = (lane & 7) + ((lane >> 3) & 1) * 8;   // A-frag row
    const int lc  = ((lane >> 4) & 1) * 4;                // A-frag col
    const int brr = ((lane >> 4) & 1) * 8 + (lane & 7);   // B-frag row
    const int bcc = ((lane >> 3) & 1) * 4;                // B-frag col

    // K/V staging mapping: 4 threads per row of 64 floats
    const int krow = tid >> 2;
    const int kcol = (tid & 3) * 16;

    // --- Stage Q (natural layout) ---
    {
        const int row = tid >> 1, half = tid & 1;
        const uint4* Qg = (const uint4*)(Q + (size_t)(q0 + row) * HID + hoff) + half * 8;
        uint4* Qs = (uint4*)&QP[row * PW + half * 32];
        #pragma unroll
        for (int j = 0; j < 8; j++) Qs[j] = Qg[j];
    }

    // --- Prologue: cp.async K tile 0 ---
    {
        unsigned d = sptr(&KB[krow * PW + kcol]);
        const float* g = K + (size_t)krow * HID + hoff + kcol;
        #pragma unroll
        for (int i = 0; i < 4; i++) CP_ASYNC16(d + i * 16, g + i * 4);
        CP_COMMIT();
    }
    __syncthreads();

    // --- Resident Q fragments via ldmatrix ---
    unsigned qa[8][4];
    {
        unsigned base = sptr(&QP[(warp * 16 + lr) * PW + lc]);
        #pragma unroll
        for (int g = 0; g < 8; g++)
            ldsm4(qa[g][0], qa[g][1], qa[g][2], qa[g][3], base + g * 32);
    }

    float o[8][4];
    #pragma unroll
    for (int nt = 0; nt < 8; nt++)
        #pragma unroll
        for (int i = 0; i < 4; i++) o[nt][i] = 0.0f;
    float mrow0 = -1e30f, mrow1 = -1e30f, lrow0 = 0.0f, lrow1 = 0.0f;

    const unsigned pbase  = sptr(&QP[(warp * 16 + lr) * PW + lc]);
    const unsigned vtbase = sptr(&VT[brr * PW + bcc]);

    for (int tile = 0; tile < S_LEN / 64; tile++) {
        const int buf = tile & 1;

        // prefetch V tile into registers
        uint4 vr[4];
        {
            const uint4* Vg = (const uint4*)(V + (size_t)(tile * 64 + krow) * HID + hoff + kcol);
            #pragma unroll
            for (int i = 0; i < 4; i++) vr[i] = Vg[i];
        }

        CP_WAIT0();            // K(tile) landed (this thread's copies)
        __syncthreads();       // prev PV done; K(tile) visible block-wide

        // transpose V into VT (d-major)
        {
            #pragma unroll
            for (int i = 0; i < 16; i++) {
                int d = (tid & 3) * 16 + i;
                unsigned val = ((const unsigned*)vr)[i];
                VT[d * PW + krow] = val;
            }
        }

        // issue next K tile
        if (tile + 1 < S_LEN / 64) {
            unsigned d = sptr(&KB[(buf ^ 1) * 64 * PW + krow * PW + kcol]);
            const float* g = K + (size_t)((tile + 1) * 64 + krow) * HID + hoff + kcol;
            #pragma unroll
            for (int i = 0; i < 4; i++) CP_ASYNC16(d + i * 16, g + i * 4);
        }
        CP_COMMIT();
        __syncthreads();       // VT visible

        // --- S = Q K^T ---
        float s[8][4];
        #pragma unroll
        for (int nt = 0; nt < 8; nt++)
            #pragma unroll
            for (int i = 0; i < 4; i++) s[nt][i] = 0.0f;

        {
            const unsigned kbase = sptr(&KB[buf * 64 * PW + brr * PW + bcc]);
            #pragma unroll
            for (int g = 0; g < 8; g++) {
                #pragma unroll
                for (int ntp = 0; ntp < 4; ntp++) {
                    unsigned b0, b1, b2, b3;
                    ldsm4(b0, b1, b2, b3, kbase + (unsigned)(ntp * 16 * PW + g * 8) * 4);
                    unsigned ba[2] = {b0, b1}, bb[2] = {b2, b3};
                    mma8(s[2 * ntp],     qa[g], ba);
                    mma8(s[2 * ntp + 1], qa[g], bb);
                }
            }
        }

        // --- Online softmax (log2 domain) ---
        float mx0 = -1e30f, mx1 = -1e30f;
        #pragma unroll
        for (int nt = 0; nt < 8; nt++) {
            s[nt][0] *= SCL2; s[nt][1] *= SCL2;
            s[nt][2] *= SCL2; s[nt][3] *= SCL2;
            mx0 = fmaxf(mx0, fmaxf(s[nt][0], s[nt][1]));
            mx1 = fmaxf(mx1, fmaxf(s[nt][2], s[nt][3]));
        }
        mx0 = fmaxf(mx0, __shfl_xor_sync(0xffffffffu, mx0, 1));
        mx0 = fmaxf(mx0, __shfl_xor_sync(0xffffffffu, mx0, 2));
        mx1 = fmaxf(mx1, __shfl_xor_sync(0xffffffffu, mx1, 1));
        mx1 = fmaxf(mx1, __shfl_xor_sync(0xffffffffu, mx1, 2));

        float mn0 = fmaxf(mrow0, mx0);
        float mn1 = fmaxf(mrow1, mx1);
        float a0 = ex2f(mrow0 - mn0);
        float a1 = ex2f(mrow1 - mn1);

        {
            const int pr = lane >> 2;
            const int pc = 2 * (lane & 3);
            unsigned* P0 = &QP[(warp * 16 + pr) * PW + pc];
            unsigned* P1 = &QP[(warp * 16 + pr + 8) * PW + pc];
            float rs0 = 0.0f, rs1 = 0.0f;
            #pragma unroll
            for (int nt = 0; nt < 8; nt++) {
                float p0 = ex2f(s[nt][0] - mn0);
                float p1 = ex2f(s[nt][1] - mn0);
                float p2 = ex2f(s[nt][2] - mn1);
                float p3 = ex2f(s[nt][3] - mn1);
                rs0 += p0 + p1;
                rs1 += p2 + p3;
                uint2 w0 = {f2tf32(p0), f2tf32(p1)};
                uint2 w1 = {f2tf32(p2), f2tf32(p3)};
                *(uint2*)(P0 + nt * 8) = w0;
                *(uint2*)(P1 + nt * 8) = w1;
            }
            rs0 += __shfl_xor_sync(0xffffffffu, rs0, 1);
            rs0 += __shfl_xor_sync(0xffffffffu, rs0, 2);
            rs1 += __shfl_xor_sync(0xffffffffu, rs1, 1);
            rs1 += __shfl_xor_sync(0xffffffffu, rs1, 2);
            lrow0 = lrow0 * a0 + rs0;
            lrow1 = lrow1 * a1 + rs1;
            mrow0 = mn0; mrow1 = mn1;
        }
        #pragma unroll
        for (int nt = 0; nt < 8; nt++) {
            o[nt][0] *= a0; o[nt][1] *= a0;
            o[nt][2] *= a1; o[nt][3] *= a1;
        }
        __syncwarp();

        // --- O += P @ V ---
        {
            #pragma unroll
            for (int g = 0; g < 8; g++) {
                unsigned pa[4];
                ldsm4(pa[0], pa[1], pa[2], pa[3], pbase + g * 32);
                #pragma unroll
                for (int ntp = 0; ntp < 4; ntp++) {
                    unsigned b0, b1, b2, b3;
                    ldsm4(b0, b1, b2, b3, vtbase + (unsigned)(ntp * 16 * PW + g * 8) * 4);
                    unsigned ba[2] = {b0, b1}, bb[2] = {b2, b3};
                    mma8(o[2 * ntp],     pa, ba);
                    mma8(o[2 * ntp + 1], pa, bb);
                }
            }
        }
        // next iteration's top __syncthreads protects VT/P reuse
    }

    // --- Write O ---
    float i0 = 1.0f / lrow0;
    float i1 = 1.0f / lrow1;
    int r0 = q0 + warp * 16 + (lane >> 2);
    #pragma unroll
    for (int nt = 0; nt < 8; nt++) {
        int c = hoff + nt * 8 + 2 * (lane & 3);
        float2 v0 = {o[nt][0] * i0, o[nt][1] * i0};
        float2 v1 = {o[nt][2] * i1, o[nt][3] * i1};
        *(float2*)&O[(size_t)r0 * HID + c] = v0;
        *(float2*)&O[(size_t)(r0 + 8) * HID + c] = v1;
    }
}

// ---------------------------------------------------------------------------
// Elementwise combine (mean of two recursive contexts)
// ---------------------------------------------------------------------------
__global__ void combine_kernel(const float4* __restrict__ a,
                               const float4* __restrict__ b,
                               float4* __restrict__ o, int n4)
{
    int i = blockIdx.x * blockDim.x + threadIdx.x;
    if (i < n4) {
        float4 x = a[i], y = b[i], r;
        r.x = 0.5f * (x.x + y.x); r.y = 0.5f * (x.y + y.y);
        r.z = 0.5f * (x.z + y.z); r.w = 0.5f * (x.w + y.w);
        o[i] = r;
    }
}

// ---------------------------------------------------------------------------
// Launch
// ---------------------------------------------------------------------------
extern "C" void kernel_launch(void* const* d_in, const int* in_sizes, int n_in,
                              void* d_out, int out_size)
{
    (void)in_sizes; (void)n_in; (void)out_size;

    const float* hs   = (const float*)d_in[0];
    const float* past = (const float*)d_in[1];
    const float* Wq = (const float*)d_in[2];  const float* bq = (const float*)d_in[3];
    const float* Wk = (const float*)d_in[4];  const float* bk = (const float*)d_in[5];
    const float* Wv = (const float*)d_in[6];  const float* bv = (const float*)d_in[7];
    const float* Wo = (const float*)d_in[8];  const float* bo = (const float*)d_in[9];
    const float* Wrq = (const float*)d_in[10]; const float* brq = (const float*)d_in[11];
    const float* Wrk = (const float*)d_in[12]; const float* brk = (const float*)d_in[13];
    const float* Wrv = (const float*)d_in[14]; const float* brv = (const float*)d_in[15];
    const float* Wg = (const float*)d_in[16];  const float* bg = (const float*)d_in[17];

    float *q, *k, *v, *ctx, *out, *rq, *rk, *rv, *rctx, *rec;
    cudaGetSymbolAddress((void**)&q,    g_q);
    cudaGetSymbolAddress((void**)&k,    g_k);
    cudaGetSymbolAddress((void**)&v,    g_v);
    cudaGetSymbolAddress((void**)&ctx,  g_ctx);
    cudaGetSymbolAddress((void**)&out,  g_out);
    cudaGetSymbolAddress((void**)&rq,   g_rq);
    cudaGetSymbolAddress((void**)&rk,   g_rk);
    cudaGetSymbolAddress((void**)&rv,   g_rv);
    cudaGetSymbolAddress((void**)&rctx, g_rctx);
    cudaGetSymbolAddress((void**)&rec,  g_rec);

    cudaFuncSetAttribute(attn_t_kernel,
                         cudaFuncAttributeMaxDynamicSharedMemorySize, ATTN_SMEM);

    dim3 agrid(S_LEN / 128, NHEAD);                 // (16, 16)
    const int n4 = SH / 4;
    const int eblk = 256;
    const int egrd = (n4 + eblk - 1) / eblk;

    // --- self attention ---
    {
        GB3 gb = {{Wq, Wk, Wv}, {bq, bk, bv}, {q, k, v}};
        gemm_b3_kernel<<<dim3(8, 32, 3), 256>>>(hs, gb, S_LEN, HID, HID, 1);
    }
    attn_t_kernel<<<agrid, 256, ATTN_SMEM>>>(q, k, v, ctx);
    {
        GB3 gb = {{Wo, 0, 0}, {bo, 0, 0}, {out, 0, 0}};
        gemm_b3_kernel<<<dim3(8, 32, 1), 256>>>(ctx, gb, S_LEN, HID, HID, 0);
    }

    // --- recursive attention ---
    {
        GB3 gb = {{Wrq, 0, 0}, {brq, 0, 0}, {rq, 0, 0}};
        gemm_b3_kernel<<<dim3(8, 32, 1), 256>>>(out, gb, S_LEN, HID, HID, 1);
    }
    {
        GB3 gb = {{Wrk, Wrv, 0}, {brk, brv, 0}, {rk, rv, 0}};
        gemm_b3_kernel<<<dim3(8, 64, 2), 256>>>(past, gb, 2 * S_LEN, HID, HID, 1);
    }
    attn_t_kernel<<<agrid, 256, ATTN_SMEM>>>(rq, rk,      rv,      rctx);
    attn_t_kernel<<<agrid, 256, ATTN_SMEM>>>(rq, rk + SH, rv + SH, rctx + SH);
    combine_kernel<<<egrd, eblk>>>((const float4*)rctx, (const float4*)(rctx + SH),
                                   (float4*)rec, n4);

    // --- fused gate + blend -> d_out ---
    gemm_gate_kernel<<<dim3(8, 32), 256>>>(out, rec, Wg, bg, (float*)d_out,
                                           S_LEN, HID);
}